// round 5
// baseline (speedup 1.0000x reference)
#include <cuda_runtime.h>
#include <math.h>

static constexpr int T    = 300;
static constexpr int KSRM = 77;
static constexpr int KREF = 11;
static constexpr int JT   = 20;   // dense psp outputs per thread

// ---------------- device-global scratch ----------------
__device__ float g_SRM[KSRM];
__device__ float g_REF[KREF];
__device__ float g_bufY[39321600];   // 131072*300
__device__ float g_bufX[9830400];
__device__ float g_bufZ[9830400];

__global__ void init_filters() {
    int i = threadIdx.x;
    if (i < KSRM) g_SRM[i] = (float)((double)i / 10.0 * exp(1.0 - (double)i / 10.0));
    if (i < KREF) g_REF[i] = (float)(-20.0 * (double)i * exp(1.0 - (double)i));
}

// ---------------- transpose (R,C) -> (C,R) ----------------
__global__ void transpose_k(const float* __restrict__ in, float* __restrict__ out,
                            int R, int C) {
    __shared__ float tile[32][33];
    int cb = blockIdx.x * 32, rb = blockIdx.y * 32;
    #pragma unroll
    for (int j = 0; j < 32; j += 8) {
        int r = rb + threadIdx.y + j, c = cb + threadIdx.x;
        tile[threadIdx.y + j][threadIdx.x] = (r < R && c < C) ? in[(size_t)r * C + c] : 0.f;
    }
    __syncthreads();
    #pragma unroll
    for (int j = 0; j < 32; j += 8) {
        int r = rb + threadIdx.x, c = cb + threadIdx.y + j;
        if (c < C && r < R) out[(size_t)c * R + r] = tile[threadIdx.x][threadIdx.y + j];
    }
}

// ---------------- sparse psp for BINARY input (bit-exact: fmaf(w,1,acc)==acc+w) ----------------
// layout (T, M); per-column sequential scan; 76-bit spike-history window.
// bit p of lo (p=0..63) => s = p+1 ; bit p of hi (p=0..11) => s = 65+p.
__global__ void __launch_bounds__(256)
psp_sparse(const float* __restrict__ in, float* __restrict__ out, int M) {
    __shared__ float ssrm[KSRM];
    for (int i = threadIdx.x; i < KSRM; i += blockDim.x) ssrm[i] = g_SRM[i];
    __syncthreads();
    int m = blockIdx.x * blockDim.x + threadIdx.x;
    if (m >= M) return;
    const float* pin = in + m;
    unsigned long long lo = 0ull;
    unsigned int hi = 0u;
    for (int t = 0; t < T; t++) {
        float acc = 0.f;
        unsigned long long w = lo;
        while (w) {                       // s ascending: 1..64
            int p = __ffsll(w);           // 1-based => s = p
            acc += ssrm[p];
            w &= w - 1;
        }
        unsigned int wh = hi;
        while (wh) {                      // s ascending: 65..76
            int p = __ffs(wh);
            acc += ssrm[64 + p];
            wh &= wh - 1;
        }
        out[(size_t)t * M + m] = acc;
        float xv = pin[(size_t)t * M];
        unsigned int b = (xv != 0.f) ? 1u : 0u;
        hi = ((hi << 1) | (unsigned int)(lo >> 63)) & 0xFFFu;
        lo = (lo << 1) | (unsigned long long)b;
    }
}

// ---------------- dense psp (pooled inputs), circular register window, no spills ----------------
template<bool INTERIOR>
__global__ void __launch_bounds__(256, 3)
psp_t(const float* __restrict__ in, float* __restrict__ out, int M, int ybase) {
    __shared__ float ssrm[KSRM];
    for (int i = threadIdx.x; i < KSRM; i += blockDim.x) ssrm[i] = g_SRM[i];
    __syncthreads();

    int m = blockIdx.x * blockDim.x + threadIdx.x;
    if (m >= M) return;
    int t0 = (blockIdx.y + ybase) * JT;
    const float* pm = in + m;

    float acc[JT];
    float xv[JT];
    #pragma unroll
    for (int j = 0; j < JT; j++) acc[j] = 0.f;
    #pragma unroll
    for (int j = 0; j < JT; j++) {
        int ti = t0 + j - 1;
        int slot = ((j - 1) % JT + JT) % JT;
        xv[slot] = (INTERIOR || ti >= 0) ? __ldg(&pm[(size_t)ti * M]) : 0.f;
    }
    #pragma unroll
    for (int s = 1; s < KSRM; s++) {
        float wt = ssrm[s];
        #pragma unroll
        for (int j = 0; j < JT; j++) {
            int slot = (((j - s) % JT) + JT) % JT;
            acc[j] = fmaf(wt, xv[slot], acc[j]);
        }
        if (s < KSRM - 1) {
            int ti = t0 - s - 1;
            int slot = (((-s - 1) % JT) + JT) % JT;
            xv[slot] = (INTERIOR || ti >= 0) ? __ldg(&pm[(size_t)ti * M]) : 0.f;
        }
    }
    #pragma unroll
    for (int j = 0; j < JT; j++) out[(size_t)(t0 + j) * M + m] = acc[j];
}

// ---------------- templated conv, smem input tile + smem weights ----------------
template<int CIN, int K, int PAD, int HIN, int WIN, int HOUT, int WOUT,
         int COUT, int OBLK, int OV, int WV>
__global__ void conv_t(const float* __restrict__ in, const float* __restrict__ wgt,
                       float* __restrict__ out, int Min, int Mout) {
    constexpr int CKK  = CIN * K * K;
    constexpr int WTHR = WOUT / WV;
    constexpr int TILE = CIN * HIN * WIN;
    __shared__ float s_in[TILE];
    __shared__ float s_w[OBLK * CKK];

    int t = blockIdx.z, n = blockIdx.y;
    int oblk0 = blockIdx.x * OBLK;
    const float* inb = in + (size_t)t * Min + (size_t)n * TILE;
    int nth = blockDim.x * blockDim.y;
    int tid = threadIdx.y * blockDim.x + threadIdx.x;
    for (int i = tid; i < TILE; i += nth) s_in[i] = inb[i];
    const float* wb = wgt + (size_t)oblk0 * CKK;
    for (int i = tid; i < OBLK * CKK; i += nth) s_w[i] = wb[i];
    __syncthreads();

    int w0 = (threadIdx.x % WTHR) * WV;
    int h  = threadIdx.x / WTHR;
    int oo = threadIdx.y * OV;

    float acc[OV][WV];
    #pragma unroll
    for (int o = 0; o < OV; o++)
        #pragma unroll
        for (int v = 0; v < WV; v++) acc[o][v] = 0.f;

    #pragma unroll 4
    for (int c = 0; c < CIN; c++) {
        #pragma unroll
        for (int kh = 0; kh < K; kh++) {
            int ih = h + kh - PAD;
            bool okh = (ih >= 0 && ih < HIN);
            float win[WV + K - 1];
            #pragma unroll
            for (int j = 0; j < WV + K - 1; j++) {
                int iw = w0 + j - PAD;
                win[j] = (okh && iw >= 0 && iw < WIN)
                       ? s_in[(c * HIN + ih) * WIN + iw] : 0.f;
            }
            #pragma unroll
            for (int kw = 0; kw < K; kw++) {
                #pragma unroll
                for (int o = 0; o < OV; o++) {
                    float wv = s_w[(oo + o) * CKK + (c * K + kh) * K + kw];
                    #pragma unroll
                    for (int v = 0; v < WV; v++)
                        acc[o][v] = fmaf(wv, win[kw + v], acc[o][v]);
                }
            }
        }
    }
    size_t ob = (size_t)t * Mout + (((size_t)n * COUT + oblk0 + oo) * HOUT + h) * WOUT + w0;
    #pragma unroll
    for (int o = 0; o < OV; o++)
        #pragma unroll
        for (int v = 0; v < WV; v++)
            out[ob + (size_t)o * (HOUT * WOUT) + v] = acc[o][v];
}

// ---------------- refractory LUT builder (oldest-first add order == reference) ----------------
__device__ __forceinline__ void build_lut(float* lut) {
    int nth = blockDim.x * blockDim.y;
    int tid = threadIdx.y * blockDim.x + threadIdx.x;
    for (int e = tid; e < 1024; e += nth) {
        float a = 0.f;
        #pragma unroll
        for (int i = 9; i >= 0; i--)
            if ((e >> i) & 1) a += g_REF[i + 1];
        lut[e] = a;
    }
    __syncthreads();
}

// ---------------- fused spike + 2x2 pool (time-major) ----------------
template<int HI, int WI>
__global__ void spikepool_lut(const float* __restrict__ u, float* __restrict__ out, int Mo) {
    __shared__ float lut[1024];
    build_lut(lut);
    int mo = blockIdx.x * blockDim.x + threadIdx.x;
    if (mo >= Mo) return;
    constexpr int WO = WI / 2, HO = HI / 2;
    int w = mo % WO; int r = mo / WO;
    int h = r % HO;  int nc = r / HO;
    int Mi = Mo * 4;
    const float* p = u + ((size_t)nc * HI + 2 * h) * WI + 2 * w;
    unsigned m0 = 0, m1 = 0, m2 = 0, m3 = 0;
    for (int t = 0; t < T; t++) {
        const float* pt = p + (size_t)t * Mi;
        float u0 = pt[0]      + lut[m0];
        float u1 = pt[1]      + lut[m1];
        float u2 = pt[WI]     + lut[m2];
        float u3 = pt[WI + 1] + lut[m3];
        bool b0 = u0 >= 10.f, b1 = u1 >= 10.f, b2 = u2 >= 10.f, b3 = u3 >= 10.f;
        float s0 = b0 ? 1.f : 0.f, s1 = b1 ? 1.f : 0.f;
        float s2 = b2 ? 1.f : 0.f, s3 = b3 ? 1.f : 0.f;
        m0 = ((m0 << 1) | (unsigned)b0) & 1023u;
        m1 = ((m1 << 1) | (unsigned)b1) & 1023u;
        m2 = ((m2 << 1) | (unsigned)b2) & 1023u;
        m3 = ((m3 << 1) | (unsigned)b3) & 1023u;
        out[(size_t)t * Mo + mo] = 2.75f * ((s0 + s1) + (s2 + s3));
    }
}

// ---------------- spike scan via LUT, in-place, time-major ----------------
__global__ void spike_lut(float* __restrict__ u, int M) {
    __shared__ float lut[1024];
    build_lut(lut);
    int m = blockIdx.x * blockDim.x + threadIdx.x;
    if (m >= M) return;
    unsigned mask = 0;
    for (int t = 0; t < T; t++) {
        float ueff = u[(size_t)t * M + m] + lut[mask];
        bool b = ueff >= 10.f;
        u[(size_t)t * M + m] = b ? 1.f : 0.f;
        mask = ((mask << 1) | (unsigned)b) & 1023u;
    }
}

// ---------------- final spike scan -> T-minor d_out ----------------
__global__ void spike_lut_out(const float* __restrict__ u, float* __restrict__ out, int M) {
    __shared__ float lut[1024];
    build_lut(lut);
    int m = blockIdx.x * blockDim.x + threadIdx.x;
    if (m >= M) return;
    unsigned mask = 0;
    for (int t = 0; t < T; t++) {
        float ueff = u[(size_t)t * M + m] + lut[mask];
        bool b = ueff >= 10.f;
        out[(size_t)m * T + t] = b ? 1.f : 0.f;
        mask = ((mask << 1) | (unsigned)b) & 1023u;
    }
}

// ---------------- dense: block per (n, 20-t group), warp per output ----------------
__global__ void dense_w(const float* __restrict__ in, const float* __restrict__ wfc,
                        float* __restrict__ out) {
    __shared__ float s_in[4096];
    int n = blockIdx.x, tg = blockIdx.y;
    int tid = threadIdx.x;                 // 320
    int o = tid >> 5, lane = tid & 31;
    const float* pw = wfc + o * 4096;
    for (int k = 0; k < 20; k++) {
        int t = tg * 20 + k;
        const float* pin = in + (size_t)t * 32768 + n * 4096;
        __syncthreads();
        for (int i = tid; i < 4096; i += 320) s_in[i] = pin[i];
        __syncthreads();
        float acc = 0.f;
        #pragma unroll 4
        for (int i = lane; i < 4096; i += 32) acc = fmaf(pw[i], s_in[i], acc);
        #pragma unroll
        for (int off = 16; off; off >>= 1) acc += __shfl_down_sync(0xffffffffu, acc, off);
        if (lane == 0) out[(size_t)t * 80 + n * 10 + o] = acc;
    }
}

// ---------------- launch ----------------
extern "C" void kernel_launch(void* const* d_in, const int* in_sizes, int n_in,
                              void* d_out, int out_size) {
    const float* x   = (const float*)d_in[0];
    const float* w1  = (const float*)d_in[1];
    const float* w2  = (const float*)d_in[2];
    const float* w3  = (const float*)d_in[3];
    const float* wfc = (const float*)d_in[4];
    float* out = (float*)d_out;

    void *pY, *pX, *pZ;
    cudaGetSymbolAddress(&pY, g_bufY);
    cudaGetSymbolAddress(&pX, g_bufX);
    cudaGetSymbolAddress(&pZ, g_bufZ);
    float* Y = (float*)pY;
    float* X = (float*)pX;
    float* Z = (float*)pZ;

    init_filters<<<1, 128>>>();

    auto pspDense = [&](const float* i, float* o, int M) {
        psp_t<false><<<dim3((M + 255) / 256, 4), 256>>>(i, o, M, 0);
        psp_t<true ><<<dim3((M + 255) / 256, T / JT - 4), 256>>>(i, o, M, 4);
    };

    // ---- input transpose: (18496, 300) -> (300, 18496) ----
    transpose_k<<<dim3((T + 31) / 32, (18496 + 31) / 32), dim3(32, 8)>>>(x, Z, 18496, T);

    // ---- layer 1: u1 = conv5x5(psp_sparse(x)); pooled = spike+pool(u1) ----
    psp_sparse<<<(18496 + 255) / 256, 256>>>(Z, X, 18496);
    conv_t<2, 5, 1, 34, 34, 32, 32, 16, 16, 4, 8>
        <<<dim3(1, 8, T), dim3(128, 4)>>>(X, w1, Y, 18496, 131072);
    spikepool_lut<32, 32><<<128, 256>>>(Y, X, 32768);

    // ---- layer 2 tail + layer 3 ----
    pspDense(X, Z, 32768);                     // pooled (non-binary) -> dense psp
    spike_lut<<<128, 256>>>(Z, 32768);         // s2 (binary)
    psp_sparse<<<(32768 + 255) / 256, 256>>>(Z, X, 32768);
    conv_t<16, 3, 1, 16, 16, 16, 16, 32, 32, 4, 8>
        <<<dim3(1, 8, T), dim3(32, 8)>>>(X, w2, Y, 32768, 65536);
    spikepool_lut<16, 16><<<64, 256>>>(Y, X, 16384);

    // ---- layer 4 tail + layer 5 ----
    pspDense(X, Z, 16384);
    spike_lut<<<64, 256>>>(Z, 16384);          // s4 (binary)
    psp_sparse<<<(16384 + 255) / 256, 256>>>(Z, X, 16384);
    conv_t<32, 3, 1, 8, 8, 8, 8, 64, 32, 4, 4>
        <<<dim3(2, 8, T), dim3(16, 8)>>>(X, w3, Y, 16384, 32768);
    spike_lut<<<128, 256>>>(Y, 32768);         // s5 (binary)

    // ---- output: spike(dense(psp_sparse(s5))) ----
    psp_sparse<<<(32768 + 255) / 256, 256>>>(Y, X, 32768);
    dense_w<<<dim3(8, 15), 320>>>(X, wfc, Z);
    spike_lut_out<<<1, 128>>>(Z, out, 80);
}

// round 6
// speedup vs baseline: 1.5905x; 1.5905x over previous
#include <cuda_runtime.h>
#include <math.h>

static constexpr int T    = 300;
static constexpr int KSRM = 77;
static constexpr int KREF = 11;
static constexpr int JT   = 20;   // psp outputs per thread (T % JT == 0)

// ---------------- device-global scratch ----------------
__device__ float g_SRM[KSRM];
__device__ float g_REF[KREF];
__device__ float g_bufY[39321600];   // 131072*300
__device__ float g_bufX[9830400];
__device__ float g_bufZ[9830400];

__global__ void init_filters() {
    int i = threadIdx.x;
    if (i < KSRM) g_SRM[i] = (float)((double)i / 10.0 * exp(1.0 - (double)i / 10.0));
    if (i < KREF) g_REF[i] = (float)(-20.0 * (double)i * exp(1.0 - (double)i));
}

// ---------------- transpose (R,C) -> (C,R) ----------------
__global__ void transpose_k(const float* __restrict__ in, float* __restrict__ out,
                            int R, int C) {
    __shared__ float tile[32][33];
    int cb = blockIdx.x * 32, rb = blockIdx.y * 32;
    #pragma unroll
    for (int j = 0; j < 32; j += 8) {
        int r = rb + threadIdx.y + j, c = cb + threadIdx.x;
        tile[threadIdx.y + j][threadIdx.x] = (r < R && c < C) ? in[(size_t)r * C + c] : 0.f;
    }
    __syncthreads();
    #pragma unroll
    for (int j = 0; j < 32; j += 8) {
        int r = rb + threadIdx.x, c = cb + threadIdx.y + j;
        if (c < C && r < R) out[(size_t)c * R + r] = tile[threadIdx.x][threadIdx.y + j];
    }
}

// ---------------- psp: 77-tap causal FIR, circular register window, JT=20 ----------------
template<bool INTERIOR>
__global__ void psp_t(const float* __restrict__ in, float* __restrict__ out,
                      int M, int ybase) {
    __shared__ float ssrm[KSRM];
    for (int i = threadIdx.x; i < KSRM; i += blockDim.x) ssrm[i] = g_SRM[i];
    __syncthreads();

    int m = blockIdx.x * blockDim.x + threadIdx.x;
    if (m >= M) return;
    int t0 = (blockIdx.y + ybase) * JT;

    float acc[JT];
    float xv[JT];
    #pragma unroll
    for (int j = 0; j < JT; j++) acc[j] = 0.f;
    // initial window: x[t0+j-1] in slot (j-1) mod JT; pointer walk (ascending)
    {
        const float* p = in + m + (size_t)(t0 - 1) * M;
        #pragma unroll
        for (int j = 0; j < JT; j++) {
            int slot = ((j - 1) % JT + JT) % JT;
            xv[slot] = (INTERIOR || (t0 + j - 1) >= 0) ? __ldg(p) : 0.f;
            p += M;
        }
    }
    const float* pd = in + m + (size_t)(t0 - 2) * M;   // descending loads
    #pragma unroll
    for (int s = 1; s < KSRM; s++) {
        float wt = ssrm[s];
        #pragma unroll
        for (int j = 0; j < JT; j++) {
            int slot = (((j - s) % JT) + JT) % JT;
            acc[j] = fmaf(wt, xv[slot], acc[j]);
        }
        if (s < KSRM - 1) {
            int slot = (((-s - 1) % JT) + JT) % JT;
            xv[slot] = (INTERIOR || (t0 - s - 1) >= 0) ? __ldg(pd) : 0.f;
            pd -= M;
        }
    }
    float* po = out + (size_t)t0 * M + m;
    #pragma unroll
    for (int j = 0; j < JT; j++) { *po = acc[j]; po += M; }
}

// ---------------- templated conv, TT timesteps per thread, smem tiles ----------------
// block: x = (WOUT/WV)*HOUT, y = OBLK/OV. grid: (COUT/OBLK, N, T/TT)
template<int CIN, int K, int PAD, int HIN, int WIN, int HOUT, int WOUT,
         int COUT, int OBLK, int OV, int WV, int TT>
__global__ void conv_t(const float* __restrict__ in, const float* __restrict__ wgt,
                       float* __restrict__ out, int Min, int Mout) {
    constexpr int CKK  = CIN * K * K;
    constexpr int WTHR = WOUT / WV;
    constexpr int TILE = CIN * HIN * WIN;
    __shared__ float s_in[TT][TILE];
    __shared__ float s_w[OBLK * CKK];

    int t0 = blockIdx.z * TT, n = blockIdx.y;
    int oblk0 = blockIdx.x * OBLK;
    int nth = blockDim.x * blockDim.y;
    int tid = threadIdx.y * blockDim.x + threadIdx.x;
    #pragma unroll
    for (int tt = 0; tt < TT; tt++) {
        const float* inb = in + (size_t)(t0 + tt) * Min + (size_t)n * TILE;
        for (int i = tid; i < TILE; i += nth) s_in[tt][i] = inb[i];
    }
    const float* wb = wgt + (size_t)oblk0 * CKK;
    for (int i = tid; i < OBLK * CKK; i += nth) s_w[i] = wb[i];
    __syncthreads();

    int w0 = (threadIdx.x % WTHR) * WV;
    int h  = threadIdx.x / WTHR;
    int oo = threadIdx.y * OV;

    float acc[TT][OV][WV];
    #pragma unroll
    for (int tt = 0; tt < TT; tt++)
        #pragma unroll
        for (int o = 0; o < OV; o++)
            #pragma unroll
            for (int v = 0; v < WV; v++) acc[tt][o][v] = 0.f;

    #pragma unroll 4
    for (int c = 0; c < CIN; c++) {
        #pragma unroll
        for (int kh = 0; kh < K; kh++) {
            int ih = h + kh - PAD;
            bool okh = (ih >= 0 && ih < HIN);
            float win[TT][WV + K - 1];
            #pragma unroll
            for (int j = 0; j < WV + K - 1; j++) {
                int iw = w0 + j - PAD;
                bool ok = okh && iw >= 0 && iw < WIN;
                #pragma unroll
                for (int tt = 0; tt < TT; tt++)
                    win[tt][j] = ok ? s_in[tt][(c * HIN + ih) * WIN + iw] : 0.f;
            }
            #pragma unroll
            for (int kw = 0; kw < K; kw++) {
                #pragma unroll
                for (int o = 0; o < OV; o++) {
                    float wv = s_w[(oo + o) * CKK + (c * K + kh) * K + kw];
                    #pragma unroll
                    for (int tt = 0; tt < TT; tt++)
                        #pragma unroll
                        for (int v = 0; v < WV; v++)
                            acc[tt][o][v] = fmaf(wv, win[tt][kw + v], acc[tt][o][v]);
                }
            }
        }
    }
    #pragma unroll
    for (int tt = 0; tt < TT; tt++) {
        size_t ob = (size_t)(t0 + tt) * Mout
                  + (((size_t)n * COUT + oblk0 + oo) * HOUT + h) * WOUT + w0;
        #pragma unroll
        for (int o = 0; o < OV; o++)
            #pragma unroll
            for (int v = 0; v < WV; v++)
                out[ob + (size_t)o * (HOUT * WOUT) + v] = acc[tt][o][v];
    }
}

// ---------------- refractory LUT (oldest-first add order == reference) ----------------
__device__ __forceinline__ void build_lut(float* lut) {
    int nth = blockDim.x * blockDim.y;
    int tid = threadIdx.y * blockDim.x + threadIdx.x;
    for (int e = tid; e < 1024; e += nth) {
        float a = 0.f;
        #pragma unroll
        for (int i = 9; i >= 0; i--)
            if ((e >> i) & 1) a += g_REF[i + 1];
        lut[e] = a;
    }
    __syncthreads();
}

// ---------------- fused spike + 2x2 pool (time-major) ----------------
template<int HI, int WI>
__global__ void spikepool_lut(const float* __restrict__ u, float* __restrict__ out, int Mo) {
    __shared__ float lut[1024];
    build_lut(lut);
    int mo = blockIdx.x * blockDim.x + threadIdx.x;
    if (mo >= Mo) return;
    constexpr int WO = WI / 2, HO = HI / 2;
    int w = mo % WO; int r = mo / WO;
    int h = r % HO;  int nc = r / HO;
    int Mi = Mo * 4;
    const float* p = u + ((size_t)nc * HI + 2 * h) * WI + 2 * w;
    unsigned m0 = 0, m1 = 0, m2 = 0, m3 = 0;
    for (int t = 0; t < T; t++) {
        const float* pt = p + (size_t)t * Mi;
        float u0 = pt[0]      + lut[m0];
        float u1 = pt[1]      + lut[m1];
        float u2 = pt[WI]     + lut[m2];
        float u3 = pt[WI + 1] + lut[m3];
        bool b0 = u0 >= 10.f, b1 = u1 >= 10.f, b2 = u2 >= 10.f, b3 = u3 >= 10.f;
        float s0 = b0 ? 1.f : 0.f, s1 = b1 ? 1.f : 0.f;
        float s2 = b2 ? 1.f : 0.f, s3 = b3 ? 1.f : 0.f;
        m0 = ((m0 << 1) | (unsigned)b0) & 1023u;
        m1 = ((m1 << 1) | (unsigned)b1) & 1023u;
        m2 = ((m2 << 1) | (unsigned)b2) & 1023u;
        m3 = ((m3 << 1) | (unsigned)b3) & 1023u;
        out[(size_t)t * Mo + mo] = 2.75f * ((s0 + s1) + (s2 + s3));
    }
}

// ---------------- spike scan via LUT, in-place, time-major ----------------
__global__ void spike_lut(float* __restrict__ u, int M) {
    __shared__ float lut[1024];
    build_lut(lut);
    int m = blockIdx.x * blockDim.x + threadIdx.x;
    if (m >= M) return;
    unsigned mask = 0;
    for (int t = 0; t < T; t++) {
        float ueff = u[(size_t)t * M + m] + lut[mask];
        bool b = ueff >= 10.f;
        u[(size_t)t * M + m] = b ? 1.f : 0.f;
        mask = ((mask << 1) | (unsigned)b) & 1023u;
    }
}

// ---------------- final spike scan -> T-minor d_out ----------------
__global__ void spike_lut_out(const float* __restrict__ u, float* __restrict__ out, int M) {
    __shared__ float lut[1024];
    build_lut(lut);
    int m = blockIdx.x * blockDim.x + threadIdx.x;
    if (m >= M) return;
    unsigned mask = 0;
    for (int t = 0; t < T; t++) {
        float ueff = u[(size_t)t * M + m] + lut[mask];
        bool b = ueff >= 10.f;
        out[(size_t)m * T + t] = b ? 1.f : 0.f;
        mask = ((mask << 1) | (unsigned)b) & 1023u;
    }
}

// ---------------- dense: block per (n, 20-t group), warp per output ----------------
__global__ void dense_w(const float* __restrict__ in, const float* __restrict__ wfc,
                        float* __restrict__ out) {
    __shared__ float s_in[4096];
    int n = blockIdx.x, tg = blockIdx.y;
    int tid = threadIdx.x;                 // 320
    int o = tid >> 5, lane = tid & 31;
    const float* pw = wfc + o * 4096;
    for (int k = 0; k < 20; k++) {
        int t = tg * 20 + k;
        const float* pin = in + (size_t)t * 32768 + n * 4096;
        __syncthreads();
        for (int i = tid; i < 4096; i += 320) s_in[i] = pin[i];
        __syncthreads();
        float acc = 0.f;
        #pragma unroll 4
        for (int i = lane; i < 4096; i += 32) acc = fmaf(pw[i], s_in[i], acc);
        #pragma unroll
        for (int off = 16; off; off >>= 1) acc += __shfl_down_sync(0xffffffffu, acc, off);
        if (lane == 0) out[(size_t)t * 80 + n * 10 + o] = acc;
    }
}

// ---------------- launch ----------------
extern "C" void kernel_launch(void* const* d_in, const int* in_sizes, int n_in,
                              void* d_out, int out_size) {
    const float* x   = (const float*)d_in[0];
    const float* w1  = (const float*)d_in[1];
    const float* w2  = (const float*)d_in[2];
    const float* w3  = (const float*)d_in[3];
    const float* wfc = (const float*)d_in[4];
    float* out = (float*)d_out;

    void *pY, *pX, *pZ;
    cudaGetSymbolAddress(&pY, g_bufY);
    cudaGetSymbolAddress(&pX, g_bufX);
    cudaGetSymbolAddress(&pZ, g_bufZ);
    float* Y = (float*)pY;
    float* X = (float*)pX;
    float* Z = (float*)pZ;

    init_filters<<<1, 128>>>();

    auto psp = [&](const float* i, float* o, int M) {
        psp_t<false><<<dim3((M + 255) / 256, 4), 256>>>(i, o, M, 0);
        psp_t<true ><<<dim3((M + 255) / 256, T / JT - 4), 256>>>(i, o, M, 4);
    };

    // ---- input transpose: (18496, 300) -> (300, 18496) ----
    transpose_k<<<dim3((T + 31) / 32, (18496 + 31) / 32), dim3(32, 8)>>>(x, Z, 18496, T);

    // ---- layer 1: u1 = conv5x5(psp(x)); pooled = spike+pool(u1) ----
    psp(Z, X, 18496);
    conv_t<2, 5, 1, 34, 34, 32, 32, 16, 16, 4, 4, 1>
        <<<dim3(1, 8, T), dim3(256, 4)>>>(X, w1, Y, 18496, 131072);
    spikepool_lut<32, 32><<<128, 256>>>(Y, X, 32768);

    // ---- layer 2 tail + layer 3 (TT=2 conv) ----
    psp(X, Z, 32768);
    spike_lut<<<128, 256>>>(Z, 32768);           // s2
    psp(Z, X, 32768);
    conv_t<16, 3, 1, 16, 16, 16, 16, 32, 32, 4, 4, 2>
        <<<dim3(1, 8, T / 2), dim3(64, 8)>>>(X, w2, Y, 32768, 65536);
    spikepool_lut<16, 16><<<64, 256>>>(Y, X, 16384);

    // ---- layer 4 tail + layer 5 (TT=2 conv) ----
    psp(X, Z, 16384);
    spike_lut<<<64, 256>>>(Z, 16384);            // s4
    psp(Z, X, 16384);
    conv_t<32, 3, 1, 8, 8, 8, 8, 64, 32, 4, 4, 2>
        <<<dim3(2, 8, T / 2), dim3(16, 8)>>>(X, w3, Y, 16384, 32768);
    spike_lut<<<128, 256>>>(Y, 32768);           // s5

    // ---- output: spike(dense(psp(s5))) ----
    psp(Y, X, 32768);
    dense_w<<<dim3(8, 15), 320>>>(X, wfc, Z);
    spike_lut_out<<<1, 128>>>(Z, out, 80);
}

// round 7
// speedup vs baseline: 1.9099x; 1.2008x over previous
#include <cuda_runtime.h>
#include <math.h>

static constexpr int T    = 300;
static constexpr int KSRM = 77;   // taps s = 0..76, SRM[0] == 0
static constexpr int KREF = 11;
static constexpr int JT   = 20;   // dense psp outputs per thread

// ---------------- device-global scratch ----------------
__device__ float g_SRM[KSRM];
__device__ float g_REF[KREF];
__device__ float g_bufY[39321600];   // 131072*300
__device__ float g_bufX[9830400];
__device__ float g_bufZ[9830400];

__global__ void init_filters() {
    int i = threadIdx.x;
    if (i < KSRM) g_SRM[i] = (float)((double)i / 10.0 * exp(1.0 - (double)i / 10.0));
    if (i < KREF) g_REF[i] = (float)(-20.0 * (double)i * exp(1.0 - (double)i));
}

// ---------------- transpose (R,C) -> (C,R) ----------------
__global__ void transpose_k(const float* __restrict__ in, float* __restrict__ out,
                            int R, int C) {
    __shared__ float tile[32][33];
    int cb = blockIdx.x * 32, rb = blockIdx.y * 32;
    #pragma unroll
    for (int j = 0; j < 32; j += 8) {
        int r = rb + threadIdx.y + j, c = cb + threadIdx.x;
        tile[threadIdx.y + j][threadIdx.x] = (r < R && c < C) ? in[(size_t)r * C + c] : 0.f;
    }
    __syncthreads();
    #pragma unroll
    for (int j = 0; j < 32; j += 8) {
        int r = rb + threadIdx.x, c = cb + threadIdx.y + j;
        if (c < C && r < R) out[(size_t)c * R + r] = tile[threadIdx.x][threadIdx.y + j];
    }
}

// ---------------- LUT builders ----------------
// refractory LUT: 10-bit spike-history mask -> refractory sum (oldest-first order)
__device__ __forceinline__ void build_rlut(float* lut) {
    int nth = blockDim.x * blockDim.y;
    int tid = threadIdx.y * blockDim.x + threadIdx.x;
    for (int e = tid; e < 1024; e += nth) {
        float a = 0.f;
        #pragma unroll
        for (int i = 9; i >= 0; i--)
            if ((e >> i) & 1) a += g_REF[i + 1];
        lut[e] = a;
    }
}

// SRM byte LUTs: slut[j][b] = sum_{i: bit i of b} SRM[8j+i+1]  (i ascending)
__device__ __forceinline__ void build_slut(float* lut) {   // [10*256]
    int nth = blockDim.x * blockDim.y;
    int tid = threadIdx.y * blockDim.x + threadIdx.x;
    for (int e = tid; e < 2560; e += nth) {
        int j = e >> 8, b = e & 255;
        float a = 0.f;
        #pragma unroll
        for (int i = 0; i < 8; i++) {
            int s = 8 * j + i + 1;
            if (s < KSRM && ((b >> i) & 1)) a += g_SRM[s];
        }
        lut[e] = a;
    }
}

// evaluate psp from 76-bit history mask (s=1..64 in lo bits 0..63, s=65..76 in hi bits 0..11)
__device__ __forceinline__ float eval_psp(const float* slut,
                                          unsigned long long lo, unsigned int hi) {
    float y = 0.f;
    #pragma unroll
    for (int j = 0; j < 8; j++)
        y += slut[j * 256 + (int)((lo >> (8 * j)) & 0xFFull)];
    y += slut[8 * 256 + (int)(hi & 0xFFu)];
    y += slut[9 * 256 + (int)((hi >> 8) & 0xFFu)];
    return y;
}

// ---------------- psp of a BINARY signal via byte LUTs (branch-free) ----------------
__global__ void psp_binary(const float* __restrict__ in, float* __restrict__ out, int M) {
    __shared__ float slut[2560];
    build_slut(slut);
    __syncthreads();
    int m = blockIdx.x * blockDim.x + threadIdx.x;
    if (m >= M) return;
    unsigned long long lo = 0ull; unsigned int hi = 0u;
    float xv = in[m];
    for (int t = 0; t < T; t++) {
        float xn = (t + 1 < T) ? in[(size_t)(t + 1) * M + m] : 0.f;   // prefetch
        out[(size_t)t * M + m] = eval_psp(slut, lo, hi);
        unsigned int b = (xv != 0.f) ? 1u : 0u;
        hi = ((hi << 1) | (unsigned int)(lo >> 63)) & 0xFFFu;
        lo = (lo << 1) | (unsigned long long)b;
        xv = xn;
    }
}

// ---------------- fused spike + psp: membrane u in -> psp(spike(u)) out ----------------
__global__ void spikepsp(const float* __restrict__ u, float* __restrict__ out, int M) {
    __shared__ float rlut[1024];
    __shared__ float slut[2560];
    build_rlut(rlut);
    build_slut(slut);
    __syncthreads();
    int m = blockIdx.x * blockDim.x + threadIdx.x;
    if (m >= M) return;
    unsigned int rm = 0;
    unsigned long long lo = 0ull; unsigned int hi = 0u;
    float uv = u[m];
    for (int t = 0; t < T; t++) {
        float un = (t + 1 < T) ? u[(size_t)(t + 1) * M + m] : 0.f;    // prefetch
        out[(size_t)t * M + m] = eval_psp(slut, lo, hi);              // spikes < t
        float ueff = uv + rlut[rm];
        unsigned int b = (ueff >= 10.f) ? 1u : 0u;
        rm = ((rm << 1) | b) & 1023u;
        hi = ((hi << 1) | (unsigned int)(lo >> 63)) & 0xFFFu;
        lo = (lo << 1) | (unsigned long long)b;
        uv = un;
    }
}

// ---------------- dense psp (pooled, non-binary inputs), JT=20 ----------------
template<bool INTERIOR>
__global__ void psp_t(const float* __restrict__ in, float* __restrict__ out,
                      int M, int ybase) {
    __shared__ float ssrm[KSRM];
    for (int i = threadIdx.x; i < KSRM; i += blockDim.x) ssrm[i] = g_SRM[i];
    __syncthreads();

    int m = blockIdx.x * blockDim.x + threadIdx.x;
    if (m >= M) return;
    int t0 = (blockIdx.y + ybase) * JT;

    float acc[JT];
    float xv[JT];
    #pragma unroll
    for (int j = 0; j < JT; j++) acc[j] = 0.f;
    {
        const float* p = in + m + (size_t)(t0 - 1) * M;
        #pragma unroll
        for (int j = 0; j < JT; j++) {
            int slot = ((j - 1) % JT + JT) % JT;
            xv[slot] = (INTERIOR || (t0 + j - 1) >= 0) ? __ldg(p) : 0.f;
            p += M;
        }
    }
    const float* pd = in + m + (size_t)(t0 - 2) * M;
    #pragma unroll
    for (int s = 1; s < KSRM; s++) {
        float wt = ssrm[s];
        #pragma unroll
        for (int j = 0; j < JT; j++) {
            int slot = (((j - s) % JT) + JT) % JT;
            acc[j] = fmaf(wt, xv[slot], acc[j]);
        }
        if (s < KSRM - 1) {
            int slot = (((-s - 1) % JT) + JT) % JT;
            xv[slot] = (INTERIOR || (t0 - s - 1) >= 0) ? __ldg(pd) : 0.f;
            pd -= M;
        }
    }
    float* po = out + (size_t)t0 * M + m;
    #pragma unroll
    for (int j = 0; j < JT; j++) { *po = acc[j]; po += M; }
}

// ---------------- templated conv, TT timesteps per thread, smem tiles ----------------
template<int CIN, int K, int PAD, int HIN, int WIN, int HOUT, int WOUT,
         int COUT, int OBLK, int OV, int WV, int TT>
__global__ void conv_t(const float* __restrict__ in, const float* __restrict__ wgt,
                       float* __restrict__ out, int Min, int Mout) {
    constexpr int CKK  = CIN * K * K;
    constexpr int WTHR = WOUT / WV;
    constexpr int TILE = CIN * HIN * WIN;
    __shared__ float s_in[TT][TILE];
    __shared__ float s_w[OBLK * CKK];

    int t0 = blockIdx.z * TT, n = blockIdx.y;
    int oblk0 = blockIdx.x * OBLK;
    int nth = blockDim.x * blockDim.y;
    int tid = threadIdx.y * blockDim.x + threadIdx.x;
    #pragma unroll
    for (int tt = 0; tt < TT; tt++) {
        const float* inb = in + (size_t)(t0 + tt) * Min + (size_t)n * TILE;
        for (int i = tid; i < TILE; i += nth) s_in[tt][i] = inb[i];
    }
    const float* wb = wgt + (size_t)oblk0 * CKK;
    for (int i = tid; i < OBLK * CKK; i += nth) s_w[i] = wb[i];
    __syncthreads();

    int w0 = (threadIdx.x % WTHR) * WV;
    int h  = threadIdx.x / WTHR;
    int oo = threadIdx.y * OV;

    float acc[TT][OV][WV];
    #pragma unroll
    for (int tt = 0; tt < TT; tt++)
        #pragma unroll
        for (int o = 0; o < OV; o++)
            #pragma unroll
            for (int v = 0; v < WV; v++) acc[tt][o][v] = 0.f;

    #pragma unroll 4
    for (int c = 0; c < CIN; c++) {
        #pragma unroll
        for (int kh = 0; kh < K; kh++) {
            int ih = h + kh - PAD;
            bool okh = (ih >= 0 && ih < HIN);
            float win[TT][WV + K - 1];
            #pragma unroll
            for (int j = 0; j < WV + K - 1; j++) {
                int iw = w0 + j - PAD;
                bool ok = okh && iw >= 0 && iw < WIN;
                #pragma unroll
                for (int tt = 0; tt < TT; tt++)
                    win[tt][j] = ok ? s_in[tt][(c * HIN + ih) * WIN + iw] : 0.f;
            }
            #pragma unroll
            for (int kw = 0; kw < K; kw++) {
                #pragma unroll
                for (int o = 0; o < OV; o++) {
                    float wv = s_w[(oo + o) * CKK + (c * K + kh) * K + kw];
                    #pragma unroll
                    for (int tt = 0; tt < TT; tt++)
                        #pragma unroll
                        for (int v = 0; v < WV; v++)
                            acc[tt][o][v] = fmaf(wv, win[tt][kw + v], acc[tt][o][v]);
                }
            }
        }
    }
    #pragma unroll
    for (int tt = 0; tt < TT; tt++) {
        size_t ob = (size_t)(t0 + tt) * Mout
                  + (((size_t)n * COUT + oblk0 + oo) * HOUT + h) * WOUT + w0;
        #pragma unroll
        for (int o = 0; o < OV; o++)
            #pragma unroll
            for (int v = 0; v < WV; v++)
                out[ob + (size_t)o * (HOUT * WOUT) + v] = acc[tt][o][v];
    }
}

// ---------------- fused spike + 2x2 pool (time-major), with prefetch ----------------
template<int HI, int WI>
__global__ void spikepool_lut(const float* __restrict__ u, float* __restrict__ out, int Mo) {
    __shared__ float lut[1024];
    build_rlut(lut);
    __syncthreads();
    int mo = blockIdx.x * blockDim.x + threadIdx.x;
    if (mo >= Mo) return;
    constexpr int WO = WI / 2, HO = HI / 2;
    int w = mo % WO; int r = mo / WO;
    int h = r % HO;  int nc = r / HO;
    int Mi = Mo * 4;
    const float* p = u + ((size_t)nc * HI + 2 * h) * WI + 2 * w;
    unsigned m0 = 0, m1 = 0, m2 = 0, m3 = 0;
    float v0 = p[0], v1 = p[1], v2 = p[WI], v3 = p[WI + 1];
    for (int t = 0; t < T; t++) {
        float n0 = 0.f, n1 = 0.f, n2 = 0.f, n3 = 0.f;
        if (t + 1 < T) {
            const float* pn = p + (size_t)(t + 1) * Mi;
            n0 = pn[0]; n1 = pn[1]; n2 = pn[WI]; n3 = pn[WI + 1];
        }
        float u0 = v0 + lut[m0];
        float u1 = v1 + lut[m1];
        float u2 = v2 + lut[m2];
        float u3 = v3 + lut[m3];
        bool b0 = u0 >= 10.f, b1 = u1 >= 10.f, b2 = u2 >= 10.f, b3 = u3 >= 10.f;
        float s0 = b0 ? 1.f : 0.f, s1 = b1 ? 1.f : 0.f;
        float s2 = b2 ? 1.f : 0.f, s3 = b3 ? 1.f : 0.f;
        m0 = ((m0 << 1) | (unsigned)b0) & 1023u;
        m1 = ((m1 << 1) | (unsigned)b1) & 1023u;
        m2 = ((m2 << 1) | (unsigned)b2) & 1023u;
        m3 = ((m3 << 1) | (unsigned)b3) & 1023u;
        out[(size_t)t * Mo + mo] = 2.75f * ((s0 + s1) + (s2 + s3));
        v0 = n0; v1 = n1; v2 = n2; v3 = n3;
    }
}

// ---------------- final spike scan -> T-minor d_out ----------------
__global__ void spike_lut_out(const float* __restrict__ u, float* __restrict__ out, int M) {
    __shared__ float lut[1024];
    build_rlut(lut);
    __syncthreads();
    int m = blockIdx.x * blockDim.x + threadIdx.x;
    if (m >= M) return;
    unsigned mask = 0;
    for (int t = 0; t < T; t++) {
        float ueff = u[(size_t)t * M + m] + lut[mask];
        bool b = ueff >= 10.f;
        out[(size_t)m * T + t] = b ? 1.f : 0.f;
        mask = ((mask << 1) | (unsigned)b) & 1023u;
    }
}

// ---------------- dense: block per (n, 20-t group), warp per output ----------------
__global__ void dense_w(const float* __restrict__ in, const float* __restrict__ wfc,
                        float* __restrict__ out) {
    __shared__ float s_in[4096];
    int n = blockIdx.x, tg = blockIdx.y;
    int tid = threadIdx.x;                 // 320
    int o = tid >> 5, lane = tid & 31;
    const float* pw = wfc + o * 4096;
    for (int k = 0; k < 20; k++) {
        int t = tg * 20 + k;
        const float* pin = in + (size_t)t * 32768 + n * 4096;
        __syncthreads();
        for (int i = tid; i < 4096; i += 320) s_in[i] = pin[i];
        __syncthreads();
        float acc = 0.f;
        #pragma unroll 4
        for (int i = lane; i < 4096; i += 32) acc = fmaf(pw[i], s_in[i], acc);
        #pragma unroll
        for (int off = 16; off; off >>= 1) acc += __shfl_down_sync(0xffffffffu, acc, off);
        if (lane == 0) out[(size_t)t * 80 + n * 10 + o] = acc;
    }
}

// ---------------- launch ----------------
extern "C" void kernel_launch(void* const* d_in, const int* in_sizes, int n_in,
                              void* d_out, int out_size) {
    const float* x   = (const float*)d_in[0];
    const float* w1  = (const float*)d_in[1];
    const float* w2  = (const float*)d_in[2];
    const float* w3  = (const float*)d_in[3];
    const float* wfc = (const float*)d_in[4];
    float* out = (float*)d_out;

    void *pY, *pX, *pZ;
    cudaGetSymbolAddress(&pY, g_bufY);
    cudaGetSymbolAddress(&pX, g_bufX);
    cudaGetSymbolAddress(&pZ, g_bufZ);
    float* Y = (float*)pY;
    float* X = (float*)pX;
    float* Z = (float*)pZ;

    init_filters<<<1, 128>>>();

    auto pspDense = [&](const float* i, float* o, int M) {
        psp_t<false><<<dim3((M + 255) / 256, 4), 256>>>(i, o, M, 0);
        psp_t<true ><<<dim3((M + 255) / 256, T / JT - 4), 256>>>(i, o, M, 4);
    };

    // ---- input transpose: (18496, 300) -> (300, 18496) ----
    transpose_k<<<dim3((T + 31) / 32, (18496 + 31) / 32), dim3(32, 8)>>>(x, Z, 18496, T);

    // ---- layer 1: u1 = conv5x5(psp(x)); pooled = spike+pool(u1) ----
    psp_binary<<<(18496 + 255) / 256, 256>>>(Z, X, 18496);
    conv_t<2, 5, 1, 34, 34, 32, 32, 16, 16, 4, 4, 1>
        <<<dim3(1, 8, T), dim3(256, 4)>>>(X, w1, Y, 18496, 131072);
    spikepool_lut<32, 32><<<128, 256>>>(Y, X, 32768);

    // ---- layer 2 tail + layer 3: u2 = psp(pooled); X = psp(spike(u2)); conv ----
    pspDense(X, Z, 32768);
    spikepsp<<<128, 256>>>(Z, X, 32768);
    conv_t<16, 3, 1, 16, 16, 16, 16, 32, 32, 4, 4, 2>
        <<<dim3(1, 8, T / 2), dim3(64, 8)>>>(X, w2, Y, 32768, 65536);
    spikepool_lut<16, 16><<<64, 256>>>(Y, X, 16384);

    // ---- layer 4 tail + layer 5 ----
    pspDense(X, Z, 16384);
    spikepsp<<<64, 256>>>(Z, X, 16384);
    conv_t<32, 3, 1, 8, 8, 8, 8, 64, 32, 4, 4, 2>
        <<<dim3(2, 8, T / 2), dim3(16, 8)>>>(X, w3, Y, 16384, 32768);

    // ---- output: X = psp(spike(u5)); dense; final spike ----
    spikepsp<<<128, 256>>>(Y, X, 32768);
    dense_w<<<dim3(8, 15), 320>>>(X, wfc, Z);
    spike_lut_out<<<1, 128>>>(Z, out, 80);
}

// round 8
// speedup vs baseline: 1.9280x; 1.0095x over previous
#include <cuda_runtime.h>
#include <math.h>

static constexpr int T    = 300;
static constexpr int KSRM = 77;   // taps s = 0..76, SRM[0] == 0
static constexpr int KREF = 11;
static constexpr int JT   = 20;   // psp outputs per thread
static constexpr int NW   = 10;   // packed spike words per neuron (ceil(300/32))

// ---------------- device-global scratch ----------------
__device__ float    g_SRM[KSRM];
__device__ float    g_REF[KREF];
__device__ float    g_bufY[39321600];
__device__ float    g_bufX[9830400];
__device__ float    g_bufZ[9830400];
__device__ unsigned g_bits[327680];   // NW * 32768 max

__global__ void init_filters() {
    int i = threadIdx.x;
    if (i < KSRM) g_SRM[i] = (float)((double)i / 10.0 * exp(1.0 - (double)i / 10.0));
    if (i < KREF) g_REF[i] = (float)(-20.0 * (double)i * exp(1.0 - (double)i));
}

// ---------------- LUT builders ----------------
__device__ __forceinline__ void build_rlut(float* lut) {
    int nth = blockDim.x * blockDim.y;
    int tid = threadIdx.y * blockDim.x + threadIdx.x;
    for (int e = tid; e < 1024; e += nth) {
        float a = 0.f;
        #pragma unroll
        for (int i = 9; i >= 0; i--)
            if ((e >> i) & 1) a += g_REF[i + 1];
        lut[e] = a;
    }
}

// slut[j][b] = sum_{i: bit i of b} SRM[8j+i+1] (i ascending)
__device__ __forceinline__ void build_slut(float* lut) {   // [10*256]
    int nth = blockDim.x * blockDim.y;
    int tid = threadIdx.y * blockDim.x + threadIdx.x;
    for (int e = tid; e < 2560; e += nth) {
        int j = e >> 8, b = e & 255;
        float a = 0.f;
        #pragma unroll
        for (int i = 0; i < 8; i++) {
            int s = 8 * j + i + 1;
            if (s < KSRM && ((b >> i) & 1)) a += g_SRM[s];
        }
        lut[e] = a;
    }
}

__device__ __forceinline__ float eval_psp(const float* slut,
                                          unsigned long long lo, unsigned int hi) {
    float y = 0.f;
    #pragma unroll
    for (int j = 0; j < 8; j++)
        y += slut[j * 256 + (int)((lo >> (8 * j)) & 0xFFull)];
    y += slut[8 * 256 + (int)(hi & 0xFFu)];
    y += slut[9 * 256 + (int)((hi >> 8) & 0xFFu)];
    return y;
}

// ---------------- pack binary input x (row-major (M,T)) into bit words ----------------
__global__ void pack_bits_rm(const float* __restrict__ x, unsigned* __restrict__ bits, int M) {
    int idx = blockIdx.x * blockDim.x + threadIdx.x;
    if (idx >= M * NW) return;
    int w = idx / M, m = idx % M;
    unsigned wd = 0;
    const float* p = x + (size_t)m * T + w * 32;
    #pragma unroll
    for (int i = 0; i < 32; i++) {
        int t = w * 32 + i;
        if (t < T) wd |= (p[i] != 0.f ? 1u : 0u) << i;
    }
    bits[(size_t)w * M + m] = wd;
}

// ---------------- spike scan (membrane -> packed spike bits), serial minimal ----------------
__global__ void spike_bits(const float* __restrict__ u, unsigned* __restrict__ bits, int M) {
    __shared__ float rlut[1024];
    build_rlut(rlut);
    __syncthreads();
    int m = blockIdx.x * blockDim.x + threadIdx.x;
    if (m >= M) return;
    unsigned rm = 0, word = 0;
    for (int t = 0; t < T; t++) {
        float ueff = u[(size_t)t * M + m] + rlut[rm];
        unsigned b = (ueff >= 10.f) ? 1u : 0u;
        rm = ((rm << 1) | b) & 1023u;
        word |= b << (t & 31);
        if ((t & 31) == 31) { bits[(size_t)(t >> 5) * M + m] = word; word = 0; }
    }
    bits[(size_t)(NW - 1) * M + m] = word;
}

// ---------------- psp from packed spike bits, t-parallel (JT=20 per thread) ----------------
__global__ void psp_frombits(const unsigned* __restrict__ bits, float* __restrict__ out, int M) {
    __shared__ float slut[2560];
    build_slut(slut);
    __syncthreads();
    int m = blockIdx.x * blockDim.x + threadIdx.x;
    if (m >= M) return;
    int t0 = blockIdx.y * JT;

    int qlo = (t0 - 76) >> 5;                 // arithmetic floor
    unsigned wl0, wl1, wl2, wl3, wl4;
    {
        int q;
        q = qlo + 0; wl0 = (q >= 0 && q < NW) ? bits[(size_t)q * M + m] : 0u;
        q = qlo + 1; wl1 = (q >= 0 && q < NW) ? bits[(size_t)q * M + m] : 0u;
        q = qlo + 2; wl2 = (q >= 0 && q < NW) ? bits[(size_t)q * M + m] : 0u;
        q = qlo + 3; wl3 = (q >= 0 && q < NW) ? bits[(size_t)q * M + m] : 0u;
        q = qlo + 4; wl4 = (q >= 0 && q < NW) ? bits[(size_t)q * M + m] : 0u;
    }
    unsigned long long w01 = (unsigned long long)wl0 | ((unsigned long long)wl1 << 32);
    unsigned long long w23 = (unsigned long long)wl2 | ((unsigned long long)wl3 << 32);
    unsigned long long w45 = (unsigned long long)wl4;

    int base = qlo << 5;
    int sh  = (t0 - 64) - base;               // in [12,43]
    int sh2 = (t0 - 76) - base;               // in [0,31]
    int sh3 = t0 - base;                      // in [76,107]

    unsigned long long W64 = (w01 >> sh) | (w23 << (64 - sh));
    unsigned long long lo = __brevll(W64);
    unsigned int W12 = (unsigned int)((w01 >> sh2) & 0xFFFull);
    unsigned int hi = __brev(W12) >> 20;
    unsigned long long stream = (w23 >> (sh3 - 64)) | (w45 << (128 - sh3));

    float* po = out + (size_t)t0 * M + m;
    #pragma unroll
    for (int k = 0; k < JT; k++) {
        *po = eval_psp(slut, lo, hi);
        po += M;
        unsigned long long b = stream & 1ull;
        stream >>= 1;
        hi = ((hi << 1) | (unsigned int)(lo >> 63)) & 0xFFFu;
        lo = (lo << 1) | b;
    }
}

// ---------------- dense psp (pooled, non-binary), JT=20 ----------------
template<bool INTERIOR>
__global__ void psp_t(const float* __restrict__ in, float* __restrict__ out,
                      int M, int ybase) {
    __shared__ float ssrm[KSRM];
    for (int i = threadIdx.x; i < KSRM; i += blockDim.x) ssrm[i] = g_SRM[i];
    __syncthreads();

    int m = blockIdx.x * blockDim.x + threadIdx.x;
    if (m >= M) return;
    int t0 = (blockIdx.y + ybase) * JT;

    float acc[JT];
    float xv[JT];
    #pragma unroll
    for (int j = 0; j < JT; j++) acc[j] = 0.f;
    {
        const float* p = in + m + (size_t)(t0 - 1) * M;
        #pragma unroll
        for (int j = 0; j < JT; j++) {
            int slot = ((j - 1) % JT + JT) % JT;
            xv[slot] = (INTERIOR || (t0 + j - 1) >= 0) ? __ldg(p) : 0.f;
            p += M;
        }
    }
    const float* pd = in + m + (size_t)(t0 - 2) * M;
    #pragma unroll
    for (int s = 1; s < KSRM; s++) {
        float wt = ssrm[s];
        #pragma unroll
        for (int j = 0; j < JT; j++) {
            int slot = (((j - s) % JT) + JT) % JT;
            acc[j] = fmaf(wt, xv[slot], acc[j]);
        }
        if (s < KSRM - 1) {
            int slot = (((-s - 1) % JT) + JT) % JT;
            xv[slot] = (INTERIOR || (t0 - s - 1) >= 0) ? __ldg(pd) : 0.f;
            pd -= M;
        }
    }
    float* po = out + (size_t)t0 * M + m;
    #pragma unroll
    for (int j = 0; j < JT; j++) { *po = acc[j]; po += M; }
}

// ---------------- padded conv: zero halo, vectorized smem loads ----------------
// PAD=1 fixed. block: x = (WOUT/WV)*HOUT, y = OBLK/OV. grid: (COUT/OBLK, N, T/TT)
template<int CIN, int K, int HIN, int WIN, int HOUT, int WOUT,
         int COUT, int OBLK, int OV, int WV, int TT>
__global__ void conv_p(const float* __restrict__ in, const float* __restrict__ wgt,
                       float* __restrict__ out, int Min, int Mout) {
    constexpr int HP    = HIN + 2;
    constexpr int WPAD  = (WIN + 2 + 3) & ~3;
    constexpr int KP    = (K + 3) & ~3;
    constexpr int TILE  = CIN * HP * WPAD;
    constexpr int WLEN  = WV + K - 1;
    constexpr int WTHR  = WOUT / WV;
    constexpr int CKK   = CIN * K * K;
    extern __shared__ float smem[];
    float* s_in = smem;                 // [TT][TILE]
    float* s_w  = smem + TT * TILE;     // [OBLK * CIN*K * KP]

    int t0 = blockIdx.z * TT, n = blockIdx.y, o0 = blockIdx.x * OBLK;
    int nth = blockDim.x * blockDim.y;
    int tid = threadIdx.y * blockDim.x + threadIdx.x;

    for (int i = tid; i < TT * TILE; i += nth) s_in[i] = 0.f;
    __syncthreads();
    #pragma unroll
    for (int tt = 0; tt < TT; tt++) {
        const float* inb = in + (size_t)(t0 + tt) * Min + (size_t)n * CIN * HIN * WIN;
        for (int i = tid; i < CIN * HIN * WIN; i += nth) {
            int c = i / (HIN * WIN), r = i % (HIN * WIN);
            int ih = r / WIN, iw = r % WIN;
            s_in[tt * TILE + (c * HP + ih + 1) * WPAD + iw + 1] = inb[i];
        }
    }
    for (int i = tid; i < OBLK * CKK; i += nth) {
        int o = i / CKK, r = i % CKK;
        int kw = r % K, row = r / K;
        s_w[(o * CIN * K + row) * KP + kw] = wgt[(size_t)(o0 + o) * CKK + r];
    }
    __syncthreads();

    int w0 = (threadIdx.x % WTHR) * WV;
    int h  = threadIdx.x / WTHR;
    int oo = threadIdx.y * OV;

    float acc[TT][OV][WV];
    #pragma unroll
    for (int tt = 0; tt < TT; tt++)
        #pragma unroll
        for (int o = 0; o < OV; o++)
            #pragma unroll
            for (int v = 0; v < WV; v++) acc[tt][o][v] = 0.f;

    #pragma unroll 2
    for (int c = 0; c < CIN; c++) {
        #pragma unroll
        for (int kh = 0; kh < K; kh++) {
            float win[TT][WLEN];
            #pragma unroll
            for (int tt = 0; tt < TT; tt++) {
                const float* bp = &s_in[tt * TILE + (c * HP + h + kh) * WPAD + w0];
                if constexpr (WLEN == 8) {
                    float4 a = *reinterpret_cast<const float4*>(bp);
                    float4 b = *reinterpret_cast<const float4*>(bp + 4);
                    win[tt][0] = a.x; win[tt][1] = a.y; win[tt][2] = a.z; win[tt][3] = a.w;
                    win[tt][4] = b.x; win[tt][5] = b.y; win[tt][6] = b.z; win[tt][7] = b.w;
                } else {   // WLEN == 6
                    float4 a = *reinterpret_cast<const float4*>(bp);
                    float2 b = *reinterpret_cast<const float2*>(bp + 4);
                    win[tt][0] = a.x; win[tt][1] = a.y; win[tt][2] = a.z; win[tt][3] = a.w;
                    win[tt][4] = b.x; win[tt][5] = b.y;
                }
            }
            #pragma unroll
            for (int o = 0; o < OV; o++) {
                const float* wp = &s_w[((oo + o) * CIN * K + c * K + kh) * KP];
                float wr[K];
                if constexpr (K == 5) {
                    float4 a = *reinterpret_cast<const float4*>(wp);
                    wr[0] = a.x; wr[1] = a.y; wr[2] = a.z; wr[3] = a.w; wr[4] = wp[4];
                } else {   // K == 3
                    float4 a = *reinterpret_cast<const float4*>(wp);
                    wr[0] = a.x; wr[1] = a.y; wr[2] = a.z;
                }
                #pragma unroll
                for (int kw = 0; kw < K; kw++)
                    #pragma unroll
                    for (int tt = 0; tt < TT; tt++)
                        #pragma unroll
                        for (int v = 0; v < WV; v++)
                            acc[tt][o][v] = fmaf(wr[kw], win[tt][kw + v], acc[tt][o][v]);
            }
        }
    }
    #pragma unroll
    for (int tt = 0; tt < TT; tt++) {
        size_t ob = (size_t)(t0 + tt) * Mout
                  + (((size_t)n * COUT + o0 + oo) * HOUT + h) * WOUT + w0;
        #pragma unroll
        for (int o = 0; o < OV; o++)
            #pragma unroll
            for (int v = 0; v < WV; v++)
                out[ob + (size_t)o * (HOUT * WOUT) + v] = acc[tt][o][v];
    }
}

// ---------------- fused spike + 2x2 pool (time-major) ----------------
template<int HI, int WI>
__global__ void spikepool_lut(const float* __restrict__ u, float* __restrict__ out, int Mo) {
    __shared__ float lut[1024];
    build_rlut(lut);
    __syncthreads();
    int mo = blockIdx.x * blockDim.x + threadIdx.x;
    if (mo >= Mo) return;
    constexpr int WO = WI / 2, HO = HI / 2;
    int w = mo % WO; int r = mo / WO;
    int h = r % HO;  int nc = r / HO;
    int Mi = Mo * 4;
    const float* p = u + ((size_t)nc * HI + 2 * h) * WI + 2 * w;
    unsigned m0 = 0, m1 = 0, m2 = 0, m3 = 0;
    float v0 = p[0], v1 = p[1], v2 = p[WI], v3 = p[WI + 1];
    for (int t = 0; t < T; t++) {
        float n0 = 0.f, n1 = 0.f, n2 = 0.f, n3 = 0.f;
        if (t + 1 < T) {
            const float* pn = p + (size_t)(t + 1) * Mi;
            n0 = pn[0]; n1 = pn[1]; n2 = pn[WI]; n3 = pn[WI + 1];
        }
        float u0 = v0 + lut[m0];
        float u1 = v1 + lut[m1];
        float u2 = v2 + lut[m2];
        float u3 = v3 + lut[m3];
        bool b0 = u0 >= 10.f, b1 = u1 >= 10.f, b2 = u2 >= 10.f, b3 = u3 >= 10.f;
        float s0 = b0 ? 1.f : 0.f, s1 = b1 ? 1.f : 0.f;
        float s2 = b2 ? 1.f : 0.f, s3 = b3 ? 1.f : 0.f;
        m0 = ((m0 << 1) | (unsigned)b0) & 1023u;
        m1 = ((m1 << 1) | (unsigned)b1) & 1023u;
        m2 = ((m2 << 1) | (unsigned)b2) & 1023u;
        m3 = ((m3 << 1) | (unsigned)b3) & 1023u;
        out[(size_t)t * Mo + mo] = 2.75f * ((s0 + s1) + (s2 + s3));
        v0 = n0; v1 = n1; v2 = n2; v3 = n3;
    }
}

// ---------------- final spike scan -> T-minor d_out ----------------
__global__ void spike_lut_out(const float* __restrict__ u, float* __restrict__ out, int M) {
    __shared__ float lut[1024];
    build_rlut(lut);
    __syncthreads();
    int m = blockIdx.x * blockDim.x + threadIdx.x;
    if (m >= M) return;
    unsigned mask = 0;
    for (int t = 0; t < T; t++) {
        float ueff = u[(size_t)t * M + m] + lut[mask];
        bool b = ueff >= 10.f;
        out[(size_t)m * T + t] = b ? 1.f : 0.f;
        mask = ((mask << 1) | (unsigned)b) & 1023u;
    }
}

// ---------------- dense: block per (n, 20-t group), warp per output ----------------
__global__ void dense_w(const float* __restrict__ in, const float* __restrict__ wfc,
                        float* __restrict__ out) {
    __shared__ float s_in[4096];
    int n = blockIdx.x, tg = blockIdx.y;
    int tid = threadIdx.x;                 // 320
    int o = tid >> 5, lane = tid & 31;
    const float* pw = wfc + o * 4096;
    for (int k = 0; k < 20; k++) {
        int t = tg * 20 + k;
        const float* pin = in + (size_t)t * 32768 + n * 4096;
        __syncthreads();
        for (int i = tid; i < 4096; i += 320) s_in[i] = pin[i];
        __syncthreads();
        float acc = 0.f;
        #pragma unroll 4
        for (int i = lane; i < 4096; i += 32) acc = fmaf(pw[i], s_in[i], acc);
        #pragma unroll
        for (int off = 16; off; off >>= 1) acc += __shfl_down_sync(0xffffffffu, acc, off);
        if (lane == 0) out[(size_t)t * 80 + n * 10 + o] = acc;
    }
}

// ---------------- launch ----------------
extern "C" void kernel_launch(void* const* d_in, const int* in_sizes, int n_in,
                              void* d_out, int out_size) {
    const float* x   = (const float*)d_in[0];
    const float* w1  = (const float*)d_in[1];
    const float* w2  = (const float*)d_in[2];
    const float* w3  = (const float*)d_in[3];
    const float* wfc = (const float*)d_in[4];
    float* out = (float*)d_out;

    void *pY, *pX, *pZ, *pB;
    cudaGetSymbolAddress(&pY, g_bufY);
    cudaGetSymbolAddress(&pX, g_bufX);
    cudaGetSymbolAddress(&pZ, g_bufZ);
    cudaGetSymbolAddress(&pB, g_bits);
    float* Y = (float*)pY;
    float* X = (float*)pX;
    float* Z = (float*)pZ;
    unsigned* B = (unsigned*)pB;

    // conv template instances + dynamic smem sizes
    auto c1 = conv_p<2, 5, 34, 34, 32, 32, 16, 16, 4, 4, 1>;
    auto c2 = conv_p<16, 3, 16, 16, 16, 16, 32, 32, 4, 4, 2>;
    auto c3 = conv_p<32, 3, 8, 8, 8, 8, 64, 32, 2, 4, 4>;
    const int s1b = (1 * 2 * 36 * 36 + 16 * 2 * 5 * 8) * 4;             // ~15.5 KB
    const int s2b = (2 * 16 * 18 * 20 + 32 * 16 * 3 * 4) * 4;           // ~70.7 KB
    const int s3b = (4 * 32 * 10 * 12 + 32 * 32 * 3 * 4) * 4;           // ~110.6 KB
    cudaFuncSetAttribute(c2, cudaFuncAttributeMaxDynamicSharedMemorySize, s2b);
    cudaFuncSetAttribute(c3, cudaFuncAttributeMaxDynamicSharedMemorySize, s3b);

    init_filters<<<1, 128>>>();

    auto pspDense = [&](const float* i, float* o, int M) {
        psp_t<false><<<dim3((M + 255) / 256, 4), 256>>>(i, o, M, 0);
        psp_t<true ><<<dim3((M + 255) / 256, T / JT - 4), 256>>>(i, o, M, 4);
    };

    // ---- layer 1: X = psp(x); Y = conv1(X); X = spike+pool(Y) ----
    pack_bits_rm<<<(18496 * NW + 255) / 256, 256>>>(x, B, 18496);
    psp_frombits<<<dim3(73, T / JT), 256>>>(B, X, 18496);
    c1<<<dim3(1, 8, T), dim3(256, 4), s1b>>>(X, w1, Y, 18496, 131072);
    spikepool_lut<32, 32><<<128, 256>>>(Y, X, 32768);

    // ---- layer 2 tail + layer 3 ----
    pspDense(X, Z, 32768);
    spike_bits<<<128, 256>>>(Z, B, 32768);
    psp_frombits<<<dim3(128, T / JT), 256>>>(B, X, 32768);
    c2<<<dim3(1, 8, T / 2), dim3(64, 8), s2b>>>(X, w2, Y, 32768, 65536);
    spikepool_lut<16, 16><<<64, 256>>>(Y, X, 16384);

    // ---- layer 4 tail + layer 5 ----
    pspDense(X, Z, 16384);
    spike_bits<<<64, 256>>>(Z, B, 16384);
    psp_frombits<<<dim3(64, T / JT), 256>>>(B, X, 16384);
    c3<<<dim3(2, 8, T / 4), dim3(16, 16), s3b>>>(X, w3, Y, 16384, 32768);

    // ---- output: X = psp(spike(u5)); dense; final spike ----
    spike_bits<<<128, 256>>>(Y, B, 32768);
    psp_frombits<<<dim3(128, T / JT), 256>>>(B, X, 32768);
    dense_w<<<dim3(8, T / JT), 320>>>(X, wfc, Z);
    spike_lut_out<<<1, 128>>>(Z, out, 80);
}